// round 15
// baseline (speedup 1.0000x reference)
#include <cuda_runtime.h>
#include <cub/cub.cuh>

#define BATCH 8
#define NPT   65536
#define TOT   (BATCH*NPT)
#define CIN   16
#define SENTV 2000000000
#define LUTB  2146689          // 129^3
#define CMASK 0x3FFFFFu        // 22-bit compact code mask
#define PPB   512

__device__ unsigned d_keys_in[TOT];
__device__ unsigned d_keys_out[TOT];
__device__ unsigned d_vals_in[TOT];
__device__ unsigned d_vals_out[TOT];
__device__ unsigned char d_cub_temp[32u<<20];
__device__ int d_isnew[TOT];
__device__ int d_prefix[TOT];
__device__ int d_blocksum[1024];
__device__ int d_blockoff[1024];
__device__ int d_batchcnt[BATCH];
__device__ int d_unq[TOT];            // slot -> compact code (only valid slots written/read)
__device__ int d_invmap[TOT];
__device__ float d_vfeat[TOT*CIN];
__device__ int d_lut[BATCH*LUTB];     // zero-init => 0 = empty, stores rank+1, indexed by cidx
__device__ unsigned long long d_pairs[27u*TOT];
__device__ unsigned d_paircnt[27];
__device__ unsigned d_chunkpfx[28];
__device__ unsigned d_totchunks;
__device__ unsigned d_pairdone;
__device__ int d_validcount;
__device__ unsigned d_originbits[3]={0xFFFFFFFFu,0xFFFFFFFFu,0xFFFFFFFFu};
__device__ float d_h1[TOT*32];
__device__ float d_h2[TOT*64];
__device__ float d_h3[(size_t)TOT*128];
__device__ double d_sumv[3][128];
__device__ double d_sumsq[3][128];
__device__ float d_bnmean[3][128];
__device__ float d_bnrstd[3][128];

// ---------- helpers ----------
__device__ __forceinline__ unsigned f2ord(float f){
    unsigned u=__float_as_uint(f);
    return (u&0x80000000u)? ~u : (u|0x80000000u);
}
__device__ __forceinline__ float ord2f(unsigned u){
    return (u&0x80000000u)? __uint_as_float(u^0x80000000u) : __uint_as_float(~u);
}
__device__ __forceinline__ unsigned long long pk2(float a,float b){
    unsigned long long r;
    asm("mov.b64 %0,{%1,%2};":"=l"(r):"f"(a),"f"(b));
    return r;
}
__device__ __forceinline__ unsigned long long dup2(float a){
    unsigned long long r;
    asm("mov.b64 %0,{%1,%1};":"=l"(r):"f"(a));
    return r;
}
__device__ __forceinline__ unsigned long long ffma2(unsigned long long a,unsigned long long b,unsigned long long c){
    unsigned long long d;
    asm("fma.rn.f32x2 %0,%1,%2,%3;":"=l"(d):"l"(a),"l"(b),"l"(c));
    return d;
}
__device__ __forceinline__ void upk2(unsigned long long v,float&a,float&b){
    asm("mov.b64 {%0,%1},%2;":"=f"(a),"=f"(b):"l"(v));
}
__device__ __forceinline__ void red4(float* addr,float a,float b,float c,float d){
    asm volatile("red.global.add.v4.f32 [%0],{%1,%2,%3,%4};"
        ::"l"(addr),"f"(a),"f"(b),"f"(c),"f"(d):"memory");
}
__device__ __forceinline__ void red2(float* addr,float a,float b){
    asm volatile("red.global.add.v2.f32 [%0],{%1,%2};"
        ::"l"(addr),"f"(a),"f"(b):"memory");
}

// ---------- per-dim min ----------
__global__ void k_min(const float* __restrict__ xyz){
    __shared__ unsigned sm0[8],sm1[8],sm2[8];
    unsigned m0=0xFFFFFFFFu,m1=0xFFFFFFFFu,m2=0xFFFFFFFFu;
    int stride=gridDim.x*blockDim.x;
    for(int p=blockIdx.x*blockDim.x+threadIdx.x;p<TOT;p+=stride){
        m0=min(m0,f2ord(xyz[3*p+0]));
        m1=min(m1,f2ord(xyz[3*p+1]));
        m2=min(m2,f2ord(xyz[3*p+2]));
    }
    m0=__reduce_min_sync(0xffffffffu,m0);
    m1=__reduce_min_sync(0xffffffffu,m1);
    m2=__reduce_min_sync(0xffffffffu,m2);
    int w=threadIdx.x>>5;
    if((threadIdx.x&31)==0){ sm0[w]=m0; sm1[w]=m1; sm2[w]=m2; }
    __syncthreads();
    if(threadIdx.x==0){
        for(int k=1;k<(int)(blockDim.x>>5);k++){
            m0=min(m0,sm0[k]); m1=min(m1,sm1[k]); m2=min(m2,sm2[k]);
        }
        atomicMin(&d_originbits[0],m0);
        atomicMin(&d_originbits[1],m1);
        atomicMin(&d_originbits[2],m2);
    }
}

// ---------- keys: compact base-129 code (order-isomorphic to base-1000) ----------
__global__ void k_keys(const float* __restrict__ xyz){
    float o0=ord2f(d_originbits[0]);
    float o1=ord2f(d_originbits[1]);
    float o2=ord2f(d_originbits[2]);
    int stride=gridDim.x*blockDim.x;
    for(int p=blockIdx.x*blockDim.x+threadIdx.x;p<TOT;p+=stride){
        int v0=(int)__fdiv_rn(xyz[3*p+0]-o0,0.4f); if(v0<0)v0=0;
        int v1=(int)__fdiv_rn(xyz[3*p+1]-o1,0.4f); if(v1<0)v1=0;
        int v2=(int)__fdiv_rn(xyz[3*p+2]-o2,0.4f); if(v2<0)v2=0;
        unsigned cidx=(unsigned)((v2*129+v1)*129+v0);
        d_keys_in[p]=((unsigned)(p>>16)<<22)|cidx;   // 22-bit code + 3-bit batch
        d_vals_in[p]=(unsigned)p;
    }
}

// ---------- scan (isnew fused into scan1) ----------
__global__ void k_scan1(){
    __shared__ int s[512];
    int tid=threadIdx.x;
    int g=blockIdx.x*512+tid;
    int nw;
    if((g&(NPT-1))==0) nw=1;
    else nw=(d_keys_out[g]!=d_keys_out[g-1])?1:0;
    d_isnew[g]=nw;
    s[tid]=nw; __syncthreads();
    #pragma unroll
    for(int off=1;off<512;off<<=1){
        int t=(tid>=off)?s[tid-off]:0;
        __syncthreads();
        s[tid]+=t;
        __syncthreads();
    }
    d_prefix[g]=s[tid];
    if(tid==511) d_blocksum[blockIdx.x]=s[511];
}
__global__ void k_scan2(){
    __shared__ int s[1024];
    int tid=threadIdx.x;
    int v=d_blocksum[tid];
    s[tid]=v; __syncthreads();
    #pragma unroll
    for(int off=1;off<1024;off<<=1){
        int t=(tid>=off)?s[tid-off]:0;
        __syncthreads();
        s[tid]+=t;
        __syncthreads();
    }
    d_blockoff[tid]=s[tid]-v;
    // batches align to 128-block boundaries (65536/512): per-batch voxel counts
    if((tid&127)==127){
        int b=tid>>7;
        d_batchcnt[b]=s[tid]-((b>0)?s[tid-128]:0);
    }
}
__device__ __forceinline__ int pfull(int i){
    return d_prefix[i]+d_blockoff[i>>9];
}

__global__ void k_build(const float* __restrict__ feat, const float* __restrict__ mask){
    int stride=gridDim.x*blockDim.x;
    for(int i=blockIdx.x*blockDim.x+threadIdx.x;i<TOT;i+=stride){
        int b=i>>16;
        unsigned key=d_keys_out[i];
        int rank=pfull(i)-pfull(b<<16);
        int g=(int)d_vals_out[i];
        d_invmap[g]=rank;
        if(d_isnew[i]){
            int cidx=(int)(key&CMASK);
            int slot=(b<<16)+rank;
            d_unq[slot]=cidx;
            d_lut[b*LUTB+cidx]=rank+1;
            float4 f0=make_float4(0,0,0,0),f1=f0,f2=f0,f3=f0;
            float cnt=0.f;
            int end=(b+1)<<16;
            for(int j=i;j<end && d_keys_out[j]==key;j++){
                int gj=(int)d_vals_out[j];
                float m=mask[gj];
                cnt+=m;
                const float4* fp=(const float4*)&feat[(size_t)gj*CIN];
                float4 a=fp[0],bb=fp[1],c=fp[2],d=fp[3];
                f0.x+=a.x*m; f0.y+=a.y*m; f0.z+=a.z*m; f0.w+=a.w*m;
                f1.x+=bb.x*m;f1.y+=bb.y*m;f1.z+=bb.z*m;f1.w+=bb.w*m;
                f2.x+=c.x*m; f2.y+=c.y*m; f2.z+=c.z*m; f2.w+=c.w*m;
                f3.x+=d.x*m; f3.y+=d.y*m; f3.z+=d.z*m; f3.w+=d.w*m;
            }
            float cn=fmaxf(cnt,1.f);
            float rC=1.0f/cn;
            f0.x*=rC;f0.y*=rC;f0.z*=rC;f0.w*=rC;
            f1.x*=rC;f1.y*=rC;f1.z*=rC;f1.w*=rC;
            f2.x*=rC;f2.y*=rC;f2.z*=rC;f2.w*=rC;
            f3.x*=rC;f3.y*=rC;f3.z*=rC;f3.w*=rC;
            float4* vp=(float4*)&d_vfeat[(size_t)slot*CIN];
            vp[0]=f0; vp[1]=f1; vp[2]=f2; vp[3]=f3;
        }
    }
}

// ---------- off-center pairs + last-block schedule ----------
__global__ void k_pairs(){
    int slot=blockIdx.x*blockDim.x+threadIdx.x;
    int lane=threadIdx.x&31;
    int b=slot>>16;
    bool vv=((slot&0xFFFF)<d_batchcnt[b]);
    int cidx=0,x=0,y=0,z=0;
    if(vv){
        cidx=d_unq[slot];
        x=cidx%129; int t=cidx/129; y=t%129; z=t/129;
    }
    #pragma unroll
    for(int ko=0;ko<27;ko++){
        if(ko==13) continue;
        int dx=(ko%3)-1, dy=((ko/3)%3)-1, dz=(ko/9)-1;
        int nx=x+dx, ny=y+dy, nz=z+dz;
        bool inb=vv && nx>=0 && ny>=0 && nz>=0 && nx<=128 && ny<=128 && nz<=128;
        int r=0;
        if(inb) r=d_lut[b*LUTB+(cidx+dx+129*dy+16641*dz)];
        bool ok=inb && (r>0);
        unsigned m=__ballot_sync(0xffffffffu,ok);
        unsigned base=0;
        if(lane==0 && m) base=atomicAdd(&d_paircnt[ko],(unsigned)__popc(m));
        base=__shfl_sync(0xffffffffu,base,0);
        if(ok){
            unsigned pos=base+__popc(m&((1u<<lane)-1u));
            d_pairs[(size_t)ko*TOT+pos]=
                ((unsigned long long)(unsigned)slot<<32)|(unsigned)((b<<16)+(r-1));
        }
    }
    // last-block election computes the chunk schedule + valid count
    __syncthreads();
    if(threadIdx.x==0){
        __threadfence();
        unsigned t=atomicAdd(&d_pairdone,1u);
        if(t==gridDim.x-1u){
            int vc=0;
            for(int bb=0;bb<BATCH;bb++) vc+=d_batchcnt[bb];
            d_validcount=vc;
            unsigned acc=0; d_chunkpfx[0]=0;
            for(int ko=0;ko<27;ko++){
                acc+=(d_paircnt[ko]+PPB-1)/PPB;
                d_chunkpfx[ko+1]=acc;
            }
            d_totchunks=acc;
            d_pairdone=0;
        }
    }
}

// ---------- hoisted BN params per lane-channel ----------
template<int BNL,int RI,int CI>
__device__ __forceinline__ void bn_hoist(int lane,const float* gam,const float* bet,
        float (&sc)[RI], float (&sh)[RI]){
    #pragma unroll
    for(int j=0;j<RI;j++){
        int c=lane+32*j;
        if constexpr(BNL>=0){
            if(c<CI){
                float a=d_bnrstd[BNL][c]*gam[c];
                sc[j]=a; sh[j]=bet[c]-d_bnmean[BNL][c]*a;
            } else { sc[j]=0.f; sh[j]=0.f; }
        } else { sc[j]=1.f; sh[j]=0.f; }
    }
}
template<int BNL>
__device__ __forceinline__ float bn_apply(float v,float sc,float sh){
    if constexpr(BNL>=0) return fmaxf(fmaf(v,sc,sh),0.f);
    else return v;
}

// ---------- center tap (V=8 for CO>=64, V=4 for CO=32); validity via batchcnt ----------
// L1 (BNL<0, CO==32) additionally clears the LUT entries (last LUT consumer was k_pairs).
template<int CI,int CO,int BNL>
__global__ void k_center(const float* __restrict__ in, float* __restrict__ out,
        const float* __restrict__ W, const float* __restrict__ bias,
        const float* __restrict__ gam, const float* __restrict__ bet){
    constexpr int RI=(CI+31)/32;
    __shared__ int sCnt[BATCH];
    int lane=threadIdx.x&31;
    if(threadIdx.x<BATCH) sCnt[threadIdx.x]=d_batchcnt[threadIdx.x];
    float sc[RI],sh[RI];
    bn_hoist<BNL,RI,CI>(lane,gam,bet,sc,sh);
    if constexpr (CO==128){
        __shared__ ulonglong2 sW[CI*32];
        for(int i=threadIdx.x;i<CI*32;i+=blockDim.x){
            int ci=i>>5, ln=i&31;
            float4 w=*(const float4*)&W[(size_t)13*CI*CO+(size_t)ci*CO+ln*4];
            sW[i]=make_ulonglong2(pk2(w.x,w.y),pk2(w.z,w.w));
        }
        __syncthreads();
        float4 bs=*(const float4*)&bias[lane*4];
        unsigned long long bias0=pk2(bs.x,bs.y), bias1=pk2(bs.z,bs.w);
        int base0=(((blockIdx.x*blockDim.x+threadIdx.x)>>5)<<3);
        int stride8=((gridDim.x*blockDim.x)>>5)<<3;
        for(int base=base0;base<TOT;base+=stride8){
            int nval=min(max(sCnt[base>>16]-(base&0xFFFF),0),8);
            float r[8][RI];
            #pragma unroll
            for(int v=0;v<8;v++)
                #pragma unroll
                for(int j=0;j<RI;j++)
                    r[v][j]=bn_apply<BNL>(in[(size_t)(base+v)*CI+lane+32*j],sc[j],sh[j]);
            unsigned long long a0[8],a1[8];
            #pragma unroll
            for(int v=0;v<8;v++){ a0[v]=bias0; a1[v]=bias1; }
            #pragma unroll
            for(int ci=0;ci<CI;ci++){
                ulonglong2 w=sW[ci*32+lane];
                #pragma unroll
                for(int v=0;v<8;v++){
                    unsigned long long ff=dup2(__shfl_sync(0xffffffffu,r[v][ci>>5],ci&31));
                    a0[v]=ffma2(ff,w.x,a0[v]);
                    a1[v]=ffma2(ff,w.y,a1[v]);
                }
            }
            #pragma unroll
            for(int v=0;v<8;v++) if(v<nval){
                float4 o; upk2(a0[v],o.x,o.y); upk2(a1[v],o.z,o.w);
                *(float4*)&out[(size_t)(base+v)*CO+lane*4]=o;
            }
        }
    } else if constexpr (CO==64){
        __shared__ unsigned long long sW[CI*32];
        for(int i=threadIdx.x;i<CI*32;i+=blockDim.x){
            int ci=i>>5, ln=i&31;
            float2 w=*(const float2*)&W[(size_t)13*CI*CO+(size_t)ci*CO+ln*2];
            sW[i]=pk2(w.x,w.y);
        }
        __syncthreads();
        float2 bs=*(const float2*)&bias[lane*2];
        unsigned long long bias0=pk2(bs.x,bs.y);
        int base0=(((blockIdx.x*blockDim.x+threadIdx.x)>>5)<<3);
        int stride8=((gridDim.x*blockDim.x)>>5)<<3;
        for(int base=base0;base<TOT;base+=stride8){
            int nval=min(max(sCnt[base>>16]-(base&0xFFFF),0),8);
            float r[8];
            #pragma unroll
            for(int v=0;v<8;v++)
                r[v]=bn_apply<BNL>(in[(size_t)(base+v)*CI+lane],sc[0],sh[0]);
            unsigned long long a0[8];
            #pragma unroll
            for(int v=0;v<8;v++) a0[v]=bias0;
            #pragma unroll
            for(int ci=0;ci<CI;ci++){
                unsigned long long w=sW[ci*32+lane];
                #pragma unroll
                for(int v=0;v<8;v++)
                    a0[v]=ffma2(dup2(__shfl_sync(0xffffffffu,r[v],ci)),w,a0[v]);
            }
            #pragma unroll
            for(int v=0;v<8;v++) if(v<nval){
                float2 o; upk2(a0[v],o.x,o.y);
                *(float2*)&out[(size_t)(base+v)*CO+lane*2]=o;
            }
        }
    } else {
        __shared__ float Ws[CI*CO];
        for(int i=threadIdx.x;i<CI*CO;i+=blockDim.x) Ws[i]=W[13*CI*CO+i];
        __syncthreads();
        float bs=bias[lane];
        int base0=(((blockIdx.x*blockDim.x+threadIdx.x)>>5)<<2);
        int stride4=((gridDim.x*blockDim.x)>>5)<<2;
        for(int base=base0;base<TOT;base+=stride4){
            int nval=min(max(sCnt[base>>16]-(base&0xFFFF),0),4);
            float r[4];
            #pragma unroll
            for(int v=0;v<4;v++)
                r[v]=(lane<CI)?bn_apply<BNL>(in[(size_t)(base+v)*CI+lane],sc[0],sh[0]):0.f;
            float acc[4]={bs,bs,bs,bs};
            #pragma unroll
            for(int ci=0;ci<CI;ci++){
                float w=Ws[ci*CO+lane];
                #pragma unroll
                for(int v=0;v<4;v++)
                    acc[v]+=__shfl_sync(0xffffffffu,r[v],ci)*w;
            }
            #pragma unroll
            for(int v=0;v<4;v++) if(v<nval)
                out[(size_t)(base+v)*CO+lane]=acc[v];
            if constexpr(BNL<0){
                // fused LUT restore (this kernel runs after k_pairs, the last LUT reader)
                if(lane<nval){
                    int slot=base+lane;
                    d_lut[(slot>>16)*LUTB+d_unq[slot]]=0;
                }
            }
        }
    }
}

// ---------- off-center scatter (unchanged champion) ----------
template<int CI,int CO,int BNL>
__global__ void k_scatter(const float* __restrict__ in, float* __restrict__ out,
        const float* __restrict__ W,
        const float* __restrict__ gam, const float* __restrict__ bet){
    constexpr int RI=(CI+31)/32;
    __shared__ int s_ko,s_base,s_cnt;
    int lane=threadIdx.x&31, warp=threadIdx.x>>5;
    int nwarps=blockDim.x>>5;
    const unsigned totc=d_totchunks;
    float sc[RI],sh[RI];
    bn_hoist<BNL,RI,CI>(lane,gam,bet,sc,sh);
    if constexpr (CO==128){
        __shared__ ulonglong2 sW[CI*32];
        for(unsigned chunk=blockIdx.x; chunk<totc; chunk+=gridDim.x){
            if(threadIdx.x==0){
                int ko=0;
                while(chunk>=d_chunkpfx[ko+1]) ko++;
                s_ko=ko;
                int base=(int)(chunk-d_chunkpfx[ko])*PPB;
                s_base=base;
                s_cnt=min(PPB,(int)d_paircnt[ko]-base);
            }
            __syncthreads();
            int ko=s_ko;
            for(int i=threadIdx.x;i<CI*32;i+=blockDim.x){
                int ci=i>>5, ln=i&31;
                float4 w=*(const float4*)&W[(size_t)ko*CI*CO+(size_t)ci*CO+ln*4];
                sW[i]=make_ulonglong2(pk2(w.x,w.y),pk2(w.z,w.w));
            }
            __syncthreads();
            int cnt=s_cnt, base=s_base;
            for(int p2=warp*8;p2<cnt;p2+=nwarps*8){
                int dst[8];
                float r[8][RI];
                #pragma unroll
                for(int v=0;v<8;v++){
                    int idx=min(p2+v,cnt-1);
                    unsigned long long pr=d_pairs[(size_t)ko*TOT+base+idx];
                    dst[v]=(int)(pr>>32);
                    int src=(int)(pr&0xFFFFFFFFu);
                    #pragma unroll
                    for(int j=0;j<RI;j++)
                        r[v][j]=bn_apply<BNL>(in[(size_t)src*CI+lane+32*j],sc[j],sh[j]);
                }
                unsigned long long a0[8]={0,0,0,0,0,0,0,0},a1[8]={0,0,0,0,0,0,0,0};
                #pragma unroll
                for(int ci=0;ci<CI;ci++){
                    ulonglong2 w=sW[ci*32+lane];
                    #pragma unroll
                    for(int v=0;v<8;v++){
                        unsigned long long ff=dup2(__shfl_sync(0xffffffffu,r[v][ci>>5],ci&31));
                        a0[v]=ffma2(ff,w.x,a0[v]);
                        a1[v]=ffma2(ff,w.y,a1[v]);
                    }
                }
                #pragma unroll
                for(int v=0;v<8;v++) if(p2+v<cnt){
                    float o0,o1,o2,o3;
                    upk2(a0[v],o0,o1); upk2(a1[v],o2,o3);
                    red4(&out[(size_t)dst[v]*CO+lane*4],o0,o1,o2,o3);
                }
            }
            __syncthreads();
        }
    } else if constexpr (CO==64){
        __shared__ unsigned long long sW[CI*32];
        for(unsigned chunk=blockIdx.x; chunk<totc; chunk+=gridDim.x){
            if(threadIdx.x==0){
                int ko=0;
                while(chunk>=d_chunkpfx[ko+1]) ko++;
                s_ko=ko;
                int base=(int)(chunk-d_chunkpfx[ko])*PPB;
                s_base=base;
                s_cnt=min(PPB,(int)d_paircnt[ko]-base);
            }
            __syncthreads();
            int ko=s_ko;
            for(int i=threadIdx.x;i<CI*32;i+=blockDim.x){
                int ci=i>>5, ln=i&31;
                float2 w=*(const float2*)&W[(size_t)ko*CI*CO+(size_t)ci*CO+ln*2];
                sW[i]=pk2(w.x,w.y);
            }
            __syncthreads();
            int cnt=s_cnt, base=s_base;
            for(int p2=warp*8;p2<cnt;p2+=nwarps*8){
                int dst[8];
                float r[8];
                #pragma unroll
                for(int v=0;v<8;v++){
                    int idx=min(p2+v,cnt-1);
                    unsigned long long pr=d_pairs[(size_t)ko*TOT+base+idx];
                    dst[v]=(int)(pr>>32);
                    int src=(int)(pr&0xFFFFFFFFu);
                    r[v]=bn_apply<BNL>(in[(size_t)src*CI+lane],sc[0],sh[0]);
                }
                unsigned long long a0[8]={0,0,0,0,0,0,0,0};
                #pragma unroll
                for(int ci=0;ci<CI;ci++){
                    unsigned long long w=sW[ci*32+lane];
                    #pragma unroll
                    for(int v=0;v<8;v++)
                        a0[v]=ffma2(dup2(__shfl_sync(0xffffffffu,r[v],ci)),w,a0[v]);
                }
                #pragma unroll
                for(int v=0;v<8;v++) if(p2+v<cnt){
                    float o0,o1; upk2(a0[v],o0,o1);
                    red2(&out[(size_t)dst[v]*CO+lane*2],o0,o1);
                }
            }
            __syncthreads();
        }
    } else {
        __shared__ float Ws[CI*CO];
        for(unsigned chunk=blockIdx.x; chunk<totc; chunk+=gridDim.x){
            if(threadIdx.x==0){
                int ko=0;
                while(chunk>=d_chunkpfx[ko+1]) ko++;
                s_ko=ko;
                int base=(int)(chunk-d_chunkpfx[ko])*PPB;
                s_base=base;
                s_cnt=min(PPB,(int)d_paircnt[ko]-base);
            }
            __syncthreads();
            int ko=s_ko;
            for(int i=threadIdx.x;i<CI*CO;i+=blockDim.x) Ws[i]=W[(size_t)ko*CI*CO+i];
            __syncthreads();
            int cnt=s_cnt, base=s_base;
            for(int p2=warp*4;p2<cnt;p2+=nwarps*4){
                int dst[4];
                float r[4];
                #pragma unroll
                for(int v=0;v<4;v++){
                    int idx=min(p2+v,cnt-1);
                    unsigned long long pr=d_pairs[(size_t)ko*TOT+base+idx];
                    dst[v]=(int)(pr>>32);
                    int src=(int)(pr&0xFFFFFFFFu);
                    r[v]=(lane<CI)?bn_apply<BNL>(in[(size_t)src*CI+lane],sc[0],sh[0]):0.f;
                }
                float acc[4]={0,0,0,0};
                #pragma unroll
                for(int ci=0;ci<CI;ci++){
                    float w=Ws[ci*CO+lane];
                    #pragma unroll
                    for(int v=0;v<4;v++)
                        acc[v]+=__shfl_sync(0xffffffffu,r[v],ci)*w;
                }
                #pragma unroll
                for(int v=0;v<4;v++) if(p2+v<cnt)
                    atomicAdd(&out[(size_t)dst[v]*CO+lane],acc[v]);
            }
            __syncthreads();
        }
    }
}

// ---------- BN stats: contiguous-validity, 2-way slot unroll for MLP ----------
template<int CO>
__global__ void k_stats(const float* __restrict__ h, int L){
    constexpr int TPS=CO/4;
    constexpr int SUBS=128/TPS;
    __shared__ int sCnt[BATCH];
    int tid=threadIdx.x;
    if(tid<BATCH) sCnt[tid]=d_batchcnt[tid];
    __syncthreads();
    int q=tid%TPS;
    int sub=tid/TPS;
    int gstep=gridDim.x*SUBS;
    float s0=0,s1=0,s2=0,s3=0,t0=0,t1=0,t2=0,t3=0;
    for(int slot=blockIdx.x*SUBS+sub; slot<TOT; slot+=gstep*2){
        int slot2=slot+gstep;
        bool v1=((slot&0xFFFF)<sCnt[slot>>16]);
        bool v2=(slot2<TOT)&&((slot2&0xFFFF)<sCnt[slot2>>16]);
        if(v1){
            float4 v=*(const float4*)&h[(size_t)slot*CO+q*4];
            s0+=v.x; s1+=v.y; s2+=v.z; s3+=v.w;
            t0+=v.x*v.x; t1+=v.y*v.y; t2+=v.z*v.z; t3+=v.w*v.w;
        }
        if(v2){
            float4 v=*(const float4*)&h[(size_t)slot2*CO+q*4];
            s0+=v.x; s1+=v.y; s2+=v.z; s3+=v.w;
            t0+=v.x*v.x; t1+=v.y*v.y; t2+=v.z*v.z; t3+=v.w*v.w;
        }
    }
    __shared__ float ss[128][8];
    ss[tid][0]=s0; ss[tid][1]=s1; ss[tid][2]=s2; ss[tid][3]=s3;
    ss[tid][4]=t0; ss[tid][5]=t1; ss[tid][6]=t2; ss[tid][7]=t3;
    __syncthreads();
    if(sub==0){
        #pragma unroll 4
        for(int k=1;k<SUBS;k++){
            s0+=ss[k*TPS+q][0]; s1+=ss[k*TPS+q][1]; s2+=ss[k*TPS+q][2]; s3+=ss[k*TPS+q][3];
            t0+=ss[k*TPS+q][4]; t1+=ss[k*TPS+q][5]; t2+=ss[k*TPS+q][6]; t3+=ss[k*TPS+q][7];
        }
        int c=q*4;
        atomicAdd(&d_sumv[L][c+0],(double)s0);
        atomicAdd(&d_sumv[L][c+1],(double)s1);
        atomicAdd(&d_sumv[L][c+2],(double)s2);
        atomicAdd(&d_sumv[L][c+3],(double)s3);
        atomicAdd(&d_sumsq[L][c+0],(double)t0);
        atomicAdd(&d_sumsq[L][c+1],(double)t1);
        atomicAdd(&d_sumsq[L][c+2],(double)t2);
        atomicAdd(&d_sumsq[L][c+3],(double)t3);
    }
}

__global__ void k_bnfinal(int L,int CO){
    int c=threadIdx.x;
    if(c<CO){
        double n=(double)max(d_validcount,1);
        double m=d_sumv[L][c]/n;
        double var=d_sumsq[L][c]/n-m*m;
        if(var<0.0) var=0.0;
        d_bnmean[L][c]=(float)m;
        d_bnrstd[L][c]=rsqrtf((float)var+1e-5f);
    }
}

// ---------- final gather + BN + mask; block 0 also resets per-launch scalars ----------
__global__ void k_out(const float* __restrict__ mask, float* __restrict__ out,
                      const float* __restrict__ gam, const float* __restrict__ bet){
    if(blockIdx.x==0){
        int t=threadIdx.x;
        if(t<27) d_paircnt[t]=0u;
        if(t<3)  d_originbits[t]=0xFFFFFFFFu;
        if(t==0) d_validcount=0;
        for(int i=t;i<384;i+=blockDim.x){
            ((double*)d_sumv)[i]=0.0; ((double*)d_sumsq)[i]=0.0;
        }
    }
    int stride=gridDim.x*blockDim.x;
    int q0=blockIdx.x*blockDim.x+threadIdx.x;
    int c4=(q0&31)*4;
    float a0=d_bnrstd[2][c4+0]*gam[c4+0], b0=bet[c4+0]-d_bnmean[2][c4+0]*a0;
    float a1=d_bnrstd[2][c4+1]*gam[c4+1], b1=bet[c4+1]-d_bnmean[2][c4+1]*a1;
    float a2=d_bnrstd[2][c4+2]*gam[c4+2], b2=bet[c4+2]-d_bnmean[2][c4+2]*a2;
    float a3=d_bnrstd[2][c4+3]*gam[c4+3], b3=bet[c4+3]-d_bnmean[2][c4+3]*a3;
    for(int q=q0; q<TOT*32; q+=stride){
        int g=q>>5;
        int slot=((g>>16)<<16)+d_invmap[g];
        float4 v=*(const float4*)&d_h3[(size_t)slot*128+c4];
        float m=mask[g];
        float4 o;
        o.x=fmaxf(fmaf(v.x,a0,b0),0.f)*m;
        o.y=fmaxf(fmaf(v.y,a1,b1),0.f)*m;
        o.z=fmaxf(fmaf(v.z,a2,b2),0.f)*m;
        o.w=fmaxf(fmaf(v.w,a3,b3),0.f)*m;
        *(float4*)&out[(size_t)q*4]=o;
    }
}

extern "C" void kernel_launch(void* const* d_in, const int* in_sizes, int n_in,
                              void* d_out, int out_size) {
    const float* xyz =(const float*)d_in[0];
    const float* feat=(const float*)d_in[1];
    const float* mask=(const float*)d_in[2];
    const float* W1=(const float*)d_in[3];
    const float* b1=(const float*)d_in[4];
    const float* g1=(const float*)d_in[5];
    const float* be1=(const float*)d_in[6];
    const float* W2=(const float*)d_in[7];
    const float* b2=(const float*)d_in[8];
    const float* g2=(const float*)d_in[9];
    const float* be2=(const float*)d_in[10];
    const float* W3=(const float*)d_in[11];
    const float* b3=(const float*)d_in[12];
    const float* g3=(const float*)d_in[13];
    const float* be3=(const float*)d_in[14];
    float* out=(float*)d_out;

    void *p_ki,*p_ko,*p_vi,*p_vo,*p_tmp;
    cudaGetSymbolAddress(&p_ki,d_keys_in);
    cudaGetSymbolAddress(&p_ko,d_keys_out);
    cudaGetSymbolAddress(&p_vi,d_vals_in);
    cudaGetSymbolAddress(&p_vo,d_vals_out);
    cudaGetSymbolAddress(&p_tmp,d_cub_temp);
    void *p_h1,*p_h2,*p_h3,*p_vf;
    cudaGetSymbolAddress(&p_h1,d_h1);
    cudaGetSymbolAddress(&p_h2,d_h2);
    cudaGetSymbolAddress(&p_h3,d_h3);
    cudaGetSymbolAddress(&p_vf,d_vfeat);
    float* h1=(float*)p_h1; float* h2=(float*)p_h2; float* h3=(float*)p_h3;
    float* vf=(float*)p_vf;

    k_min<<<256,256>>>(xyz);
    k_keys<<<1024,256>>>(xyz);
    size_t tmp_bytes=32u<<20;
    // 25-bit keys: 22-bit compact code + 3-bit batch
    cub::DeviceRadixSort::SortPairs(p_tmp,tmp_bytes,
        (const unsigned*)p_ki,(unsigned*)p_ko,
        (const unsigned*)p_vi,(unsigned*)p_vo,
        TOT,0,25,(cudaStream_t)0);
    k_scan1<<<1024,512>>>();
    k_scan2<<<1,1024>>>();
    k_build<<<2048,256>>>(feat,mask);
    k_pairs<<<2048,256>>>();   // also computes chunk schedule in last block

    // Layer 1: 16 -> 32 (center also restores LUT to zeros)
    k_center<CIN,32,-1><<<2048,256>>>(vf,h1,W1,b1,nullptr,nullptr);
    k_scatter<CIN,32,-1><<<2048,256>>>(vf,h1,W1,nullptr,nullptr);
    k_stats<32><<<2048,128>>>(h1,0);
    k_bnfinal<<<1,128>>>(0,32);
    // Layer 2: 32 -> 64 (fuses BN0+relu on input)
    k_center<32,64,0><<<2048,256>>>(h1,h2,W2,b2,g1,be1);
    k_scatter<32,64,0><<<2048,256>>>(h1,h2,W2,g1,be1);
    k_stats<64><<<2048,128>>>(h2,1);
    k_bnfinal<<<1,128>>>(1,64);
    // Layer 3: 64 -> 128 (fuses BN1+relu on input)
    k_center<64,128,1><<<2048,256>>>(h2,h3,W3,b3,g2,be2);
    k_scatter<64,128,1><<<2048,256>>>(h2,h3,W3,g2,be2);
    k_stats<128><<<2048,128>>>(h3,2);
    k_bnfinal<<<1,128>>>(2,128);
    // Final: BN2+relu + gather by inv + mask (+ per-launch scalar resets in block 0)
    k_out<<<8192,256>>>(mask,out,g3,be3);
}

// round 16
// speedup vs baseline: 1.0244x; 1.0244x over previous
#include <cuda_runtime.h>
#include <cub/cub.cuh>

#define BATCH 8
#define NPT   65536
#define TOT   (BATCH*NPT)
#define CIN   16
#define SENTV 2000000000
#define LUTB  2146689          // 129^3
#define CMASK 0x3FFFFFu        // 22-bit compact code mask
#define PPB   512

__device__ unsigned d_keys_in[TOT];
__device__ unsigned d_keys_out[TOT];
__device__ unsigned d_vals_in[TOT];
__device__ unsigned d_vals_out[TOT];
__device__ unsigned char d_cub_temp[32u<<20];
__device__ int d_isnew[TOT];
__device__ int d_prefix[TOT];
__device__ int d_blocksum[1024];
__device__ int d_blockoff[1024];
__device__ int d_batchcnt[BATCH];
__device__ int d_unq[TOT];            // slot -> compact code (only valid slots written/read)
__device__ int d_invmap[TOT];
__device__ float d_vfeat[TOT*CIN];
__device__ int d_lut[BATCH*LUTB];     // zero-init => 0 = empty, stores rank+1, indexed by cidx
__device__ unsigned long long d_pairs[27u*TOT];
__device__ unsigned d_paircnt[27];
__device__ unsigned d_chunkpfx[28];
__device__ unsigned d_totchunks;
__device__ int d_validcount;
__device__ unsigned d_originbits[3];
__device__ float d_h1[TOT*32];
__device__ float d_h2[TOT*64];
__device__ float d_h3[(size_t)TOT*128];
__device__ double d_sumv[3][128];
__device__ double d_sumsq[3][128];
__device__ float d_bnmean[3][128];
__device__ float d_bnrstd[3][128];

// ---------- helpers ----------
__device__ __forceinline__ unsigned f2ord(float f){
    unsigned u=__float_as_uint(f);
    return (u&0x80000000u)? ~u : (u|0x80000000u);
}
__device__ __forceinline__ float ord2f(unsigned u){
    return (u&0x80000000u)? __uint_as_float(u^0x80000000u) : __uint_as_float(~u);
}
__device__ __forceinline__ unsigned long long pk2(float a,float b){
    unsigned long long r;
    asm("mov.b64 %0,{%1,%2};":"=l"(r):"f"(a),"f"(b));
    return r;
}
__device__ __forceinline__ unsigned long long dup2(float a){
    unsigned long long r;
    asm("mov.b64 %0,{%1,%1};":"=l"(r):"f"(a));
    return r;
}
__device__ __forceinline__ unsigned long long ffma2(unsigned long long a,unsigned long long b,unsigned long long c){
    unsigned long long d;
    asm("fma.rn.f32x2 %0,%1,%2,%3;":"=l"(d):"l"(a),"l"(b),"l"(c));
    return d;
}
__device__ __forceinline__ void upk2(unsigned long long v,float&a,float&b){
    asm("mov.b64 {%0,%1},%2;":"=f"(a),"=f"(b):"l"(v));
}
__device__ __forceinline__ void red4(float* addr,float a,float b,float c,float d){
    asm volatile("red.global.add.v4.f32 [%0],{%1,%2,%3,%4};"
        ::"l"(addr),"f"(a),"f"(b),"f"(c),"f"(d):"memory");
}
__device__ __forceinline__ void red2(float* addr,float a,float b){
    asm volatile("red.global.add.v2.f32 [%0],{%1,%2};"
        ::"l"(addr),"f"(a),"f"(b):"memory");
}

// ---------- init: tiny (no big clears; LUT maintained-zero; unq only valid-read) ----------
__global__ void k_init(){
    int t=threadIdx.x;
    if(t<27)  d_paircnt[t]=0u;
    if(t<3)   d_originbits[t]=0xFFFFFFFFu;
    if(t==0)  d_validcount=0;
    for(int i=t;i<384;i+=blockDim.x){
        ((double*)d_sumv)[i]=0.0; ((double*)d_sumsq)[i]=0.0;
    }
}

// ---------- per-dim min ----------
__global__ void k_min(const float* __restrict__ xyz){
    __shared__ unsigned sm0[8],sm1[8],sm2[8];
    unsigned m0=0xFFFFFFFFu,m1=0xFFFFFFFFu,m2=0xFFFFFFFFu;
    int stride=gridDim.x*blockDim.x;
    for(int p=blockIdx.x*blockDim.x+threadIdx.x;p<TOT;p+=stride){
        m0=min(m0,f2ord(xyz[3*p+0]));
        m1=min(m1,f2ord(xyz[3*p+1]));
        m2=min(m2,f2ord(xyz[3*p+2]));
    }
    m0=__reduce_min_sync(0xffffffffu,m0);
    m1=__reduce_min_sync(0xffffffffu,m1);
    m2=__reduce_min_sync(0xffffffffu,m2);
    int w=threadIdx.x>>5;
    if((threadIdx.x&31)==0){ sm0[w]=m0; sm1[w]=m1; sm2[w]=m2; }
    __syncthreads();
    if(threadIdx.x==0){
        for(int k=1;k<(int)(blockDim.x>>5);k++){
            m0=min(m0,sm0[k]); m1=min(m1,sm1[k]); m2=min(m2,sm2[k]);
        }
        atomicMin(&d_originbits[0],m0);
        atomicMin(&d_originbits[1],m1);
        atomicMin(&d_originbits[2],m2);
    }
}

// ---------- keys: compact base-129 code (order-isomorphic to base-1000) ----------
__global__ void k_keys(const float* __restrict__ xyz){
    float o0=ord2f(d_originbits[0]);
    float o1=ord2f(d_originbits[1]);
    float o2=ord2f(d_originbits[2]);
    int stride=gridDim.x*blockDim.x;
    for(int p=blockIdx.x*blockDim.x+threadIdx.x;p<TOT;p+=stride){
        int v0=(int)__fdiv_rn(xyz[3*p+0]-o0,0.4f); if(v0<0)v0=0;
        int v1=(int)__fdiv_rn(xyz[3*p+1]-o1,0.4f); if(v1<0)v1=0;
        int v2=(int)__fdiv_rn(xyz[3*p+2]-o2,0.4f); if(v2<0)v2=0;
        unsigned cidx=(unsigned)((v2*129+v1)*129+v0);
        d_keys_in[p]=((unsigned)(p>>16)<<22)|cidx;   // 22-bit code + 3-bit batch
        d_vals_in[p]=(unsigned)p;
    }
}

// ---------- scan (isnew fused into scan1) ----------
__global__ void k_scan1(){
    __shared__ int s[512];
    int tid=threadIdx.x;
    int g=blockIdx.x*512+tid;
    int nw;
    if((g&(NPT-1))==0) nw=1;
    else nw=(d_keys_out[g]!=d_keys_out[g-1])?1:0;
    d_isnew[g]=nw;
    s[tid]=nw; __syncthreads();
    #pragma unroll
    for(int off=1;off<512;off<<=1){
        int t=(tid>=off)?s[tid-off]:0;
        __syncthreads();
        s[tid]+=t;
        __syncthreads();
    }
    d_prefix[g]=s[tid];
    if(tid==511) d_blocksum[blockIdx.x]=s[511];
}
__global__ void k_scan2(){
    __shared__ int s[1024];
    int tid=threadIdx.x;
    int v=d_blocksum[tid];
    s[tid]=v; __syncthreads();
    #pragma unroll
    for(int off=1;off<1024;off<<=1){
        int t=(tid>=off)?s[tid-off]:0;
        __syncthreads();
        s[tid]+=t;
        __syncthreads();
    }
    d_blockoff[tid]=s[tid]-v;
    // batches align to 128-block boundaries (65536/512): per-batch voxel counts
    if((tid&127)==127){
        int b=tid>>7;
        d_batchcnt[b]=s[tid]-((b>0)?s[tid-128]:0);
    }
}
__device__ __forceinline__ int pfull(int i){
    return d_prefix[i]+d_blockoff[i>>9];
}

__global__ void k_build(const float* __restrict__ feat, const float* __restrict__ mask){
    int stride=gridDim.x*blockDim.x;
    for(int i=blockIdx.x*blockDim.x+threadIdx.x;i<TOT;i+=stride){
        int b=i>>16;
        unsigned key=d_keys_out[i];
        int rank=pfull(i)-pfull(b<<16);
        int g=(int)d_vals_out[i];
        d_invmap[g]=rank;
        if(d_isnew[i]){
            int cidx=(int)(key&CMASK);
            int slot=(b<<16)+rank;
            d_unq[slot]=cidx;
            d_lut[b*LUTB+cidx]=rank+1;
            float4 f0=make_float4(0,0,0,0),f1=f0,f2=f0,f3=f0;
            float cnt=0.f;
            int end=(b+1)<<16;
            for(int j=i;j<end && d_keys_out[j]==key;j++){
                int gj=(int)d_vals_out[j];
                float m=mask[gj];
                cnt+=m;
                const float4* fp=(const float4*)&feat[(size_t)gj*CIN];
                float4 a=fp[0],bb=fp[1],c=fp[2],d=fp[3];
                f0.x+=a.x*m; f0.y+=a.y*m; f0.z+=a.z*m; f0.w+=a.w*m;
                f1.x+=bb.x*m;f1.y+=bb.y*m;f1.z+=bb.z*m;f1.w+=bb.w*m;
                f2.x+=c.x*m; f2.y+=c.y*m; f2.z+=c.z*m; f2.w+=c.w*m;
                f3.x+=d.x*m; f3.y+=d.y*m; f3.z+=d.z*m; f3.w+=d.w*m;
            }
            float cn=fmaxf(cnt,1.f);
            float rC=1.0f/cn;
            f0.x*=rC;f0.y*=rC;f0.z*=rC;f0.w*=rC;
            f1.x*=rC;f1.y*=rC;f1.z*=rC;f1.w*=rC;
            f2.x*=rC;f2.y*=rC;f2.z*=rC;f2.w*=rC;
            f3.x*=rC;f3.y*=rC;f3.z*=rC;f3.w*=rC;
            float4* vp=(float4*)&d_vfeat[(size_t)slot*CIN];
            vp[0]=f0; vp[1]=f1; vp[2]=f2; vp[3]=f3;
        }
    }
}

// ---------- off-center pairs: contiguous-validity, warp-aggregated atomics ----------
__global__ void k_pairs(){
    int slot=blockIdx.x*blockDim.x+threadIdx.x;
    int lane=threadIdx.x&31;
    int b=slot>>16;
    bool vv=((slot&0xFFFF)<d_batchcnt[b]);
    int cidx=0,x=0,y=0,z=0;
    if(vv){
        cidx=d_unq[slot];
        x=cidx%129; int t=cidx/129; y=t%129; z=t/129;
    }
    #pragma unroll
    for(int ko=0;ko<27;ko++){
        if(ko==13) continue;
        int dx=(ko%3)-1, dy=((ko/3)%3)-1, dz=(ko/9)-1;
        int nx=x+dx, ny=y+dy, nz=z+dz;
        bool inb=vv && nx>=0 && ny>=0 && nz>=0 && nx<=128 && ny<=128 && nz<=128;
        int r=0;
        if(inb) r=d_lut[b*LUTB+(cidx+dx+129*dy+16641*dz)];
        bool ok=inb && (r>0);
        unsigned m=__ballot_sync(0xffffffffu,ok);
        unsigned base=0;
        if(lane==0 && m) base=atomicAdd(&d_paircnt[ko],(unsigned)__popc(m));
        base=__shfl_sync(0xffffffffu,base,0);
        if(ok){
            unsigned pos=base+__popc(m&((1u<<lane)-1u));
            d_pairs[(size_t)ko*TOT+pos]=
                ((unsigned long long)(unsigned)slot<<32)|(unsigned)((b<<16)+(r-1));
        }
    }
}

__global__ void k_unclear(){
    int stride=gridDim.x*blockDim.x;
    for(int slot=blockIdx.x*blockDim.x+threadIdx.x;slot<TOT;slot+=stride){
        if((slot&0xFFFF)<d_batchcnt[slot>>16])
            d_lut[(slot>>16)*LUTB+d_unq[slot]]=0;
    }
}

__global__ void k_sched(){
    if(threadIdx.x==0&&blockIdx.x==0){
        int vc=0;
        for(int b=0;b<BATCH;b++) vc+=d_batchcnt[b];
        d_validcount=vc;
        unsigned acc=0; d_chunkpfx[0]=0;
        for(int ko=0;ko<27;ko++){
            acc+=(d_paircnt[ko]+PPB-1)/PPB;
            d_chunkpfx[ko+1]=acc;
        }
        d_totchunks=acc;
    }
}

// ---------- hoisted BN params per lane-channel ----------
template<int BNL,int RI,int CI>
__device__ __forceinline__ void bn_hoist(int lane,const float* gam,const float* bet,
        float (&sc)[RI], float (&sh)[RI]){
    #pragma unroll
    for(int j=0;j<RI;j++){
        int c=lane+32*j;
        if constexpr(BNL>=0){
            if(c<CI){
                float a=d_bnrstd[BNL][c]*gam[c];
                sc[j]=a; sh[j]=bet[c]-d_bnmean[BNL][c]*a;
            } else { sc[j]=0.f; sh[j]=0.f; }
        } else { sc[j]=1.f; sh[j]=0.f; }
    }
}
template<int BNL>
__device__ __forceinline__ float bn_apply(float v,float sc,float sh){
    if constexpr(BNL>=0) return fmaxf(fmaf(v,sc,sh),0.f);
    else return v;
}

// ---------- center tap (V=8 for CO>=64, V=4 for CO=32); validity via batchcnt ----------
template<int CI,int CO,int BNL>
__global__ void k_center(const float* __restrict__ in, float* __restrict__ out,
        const float* __restrict__ W, const float* __restrict__ bias,
        const float* __restrict__ gam, const float* __restrict__ bet){
    constexpr int RI=(CI+31)/32;
    __shared__ int sCnt[BATCH];
    int lane=threadIdx.x&31;
    if(threadIdx.x<BATCH) sCnt[threadIdx.x]=d_batchcnt[threadIdx.x];
    float sc[RI],sh[RI];
    bn_hoist<BNL,RI,CI>(lane,gam,bet,sc,sh);
    if constexpr (CO==128){
        __shared__ ulonglong2 sW[CI*32];
        for(int i=threadIdx.x;i<CI*32;i+=blockDim.x){
            int ci=i>>5, ln=i&31;
            float4 w=*(const float4*)&W[(size_t)13*CI*CO+(size_t)ci*CO+ln*4];
            sW[i]=make_ulonglong2(pk2(w.x,w.y),pk2(w.z,w.w));
        }
        __syncthreads();
        float4 bs=*(const float4*)&bias[lane*4];
        unsigned long long bias0=pk2(bs.x,bs.y), bias1=pk2(bs.z,bs.w);
        int base0=(((blockIdx.x*blockDim.x+threadIdx.x)>>5)<<3);
        int stride8=((gridDim.x*blockDim.x)>>5)<<3;
        for(int base=base0;base<TOT;base+=stride8){
            int nval=min(max(sCnt[base>>16]-(base&0xFFFF),0),8);
            float r[8][RI];
            #pragma unroll
            for(int v=0;v<8;v++)
                #pragma unroll
                for(int j=0;j<RI;j++)
                    r[v][j]=bn_apply<BNL>(in[(size_t)(base+v)*CI+lane+32*j],sc[j],sh[j]);
            unsigned long long a0[8],a1[8];
            #pragma unroll
            for(int v=0;v<8;v++){ a0[v]=bias0; a1[v]=bias1; }
            #pragma unroll
            for(int ci=0;ci<CI;ci++){
                ulonglong2 w=sW[ci*32+lane];
                #pragma unroll
                for(int v=0;v<8;v++){
                    unsigned long long ff=dup2(__shfl_sync(0xffffffffu,r[v][ci>>5],ci&31));
                    a0[v]=ffma2(ff,w.x,a0[v]);
                    a1[v]=ffma2(ff,w.y,a1[v]);
                }
            }
            #pragma unroll
            for(int v=0;v<8;v++) if(v<nval){
                float4 o; upk2(a0[v],o.x,o.y); upk2(a1[v],o.z,o.w);
                *(float4*)&out[(size_t)(base+v)*CO+lane*4]=o;
            }
        }
    } else if constexpr (CO==64){
        __shared__ unsigned long long sW[CI*32];
        for(int i=threadIdx.x;i<CI*32;i+=blockDim.x){
            int ci=i>>5, ln=i&31;
            float2 w=*(const float2*)&W[(size_t)13*CI*CO+(size_t)ci*CO+ln*2];
            sW[i]=pk2(w.x,w.y);
        }
        __syncthreads();
        float2 bs=*(const float2*)&bias[lane*2];
        unsigned long long bias0=pk2(bs.x,bs.y);
        int base0=(((blockIdx.x*blockDim.x+threadIdx.x)>>5)<<3);
        int stride8=((gridDim.x*blockDim.x)>>5)<<3;
        for(int base=base0;base<TOT;base+=stride8){
            int nval=min(max(sCnt[base>>16]-(base&0xFFFF),0),8);
            float r[8];
            #pragma unroll
            for(int v=0;v<8;v++)
                r[v]=bn_apply<BNL>(in[(size_t)(base+v)*CI+lane],sc[0],sh[0]);
            unsigned long long a0[8];
            #pragma unroll
            for(int v=0;v<8;v++) a0[v]=bias0;
            #pragma unroll
            for(int ci=0;ci<CI;ci++){
                unsigned long long w=sW[ci*32+lane];
                #pragma unroll
                for(int v=0;v<8;v++)
                    a0[v]=ffma2(dup2(__shfl_sync(0xffffffffu,r[v],ci)),w,a0[v]);
            }
            #pragma unroll
            for(int v=0;v<8;v++) if(v<nval){
                float2 o; upk2(a0[v],o.x,o.y);
                *(float2*)&out[(size_t)(base+v)*CO+lane*2]=o;
            }
        }
    } else {
        __shared__ float Ws[CI*CO];
        for(int i=threadIdx.x;i<CI*CO;i+=blockDim.x) Ws[i]=W[13*CI*CO+i];
        __syncthreads();
        float bs=bias[lane];
        int base0=(((blockIdx.x*blockDim.x+threadIdx.x)>>5)<<2);
        int stride4=((gridDim.x*blockDim.x)>>5)<<2;
        for(int base=base0;base<TOT;base+=stride4){
            int nval=min(max(sCnt[base>>16]-(base&0xFFFF),0),4);
            float r[4];
            #pragma unroll
            for(int v=0;v<4;v++)
                r[v]=(lane<CI)?bn_apply<BNL>(in[(size_t)(base+v)*CI+lane],sc[0],sh[0]):0.f;
            float acc[4]={bs,bs,bs,bs};
            #pragma unroll
            for(int ci=0;ci<CI;ci++){
                float w=Ws[ci*CO+lane];
                #pragma unroll
                for(int v=0;v<4;v++)
                    acc[v]+=__shfl_sync(0xffffffffu,r[v],ci)*w;
            }
            #pragma unroll
            for(int v=0;v<4;v++) if(v<nval)
                out[(size_t)(base+v)*CO+lane]=acc[v];
        }
    }
}

// ---------- off-center scatter (champion) ----------
template<int CI,int CO,int BNL>
__global__ void k_scatter(const float* __restrict__ in, float* __restrict__ out,
        const float* __restrict__ W,
        const float* __restrict__ gam, const float* __restrict__ bet){
    constexpr int RI=(CI+31)/32;
    __shared__ int s_ko,s_base,s_cnt;
    int lane=threadIdx.x&31, warp=threadIdx.x>>5;
    int nwarps=blockDim.x>>5;
    const unsigned totc=d_totchunks;
    float sc[RI],sh[RI];
    bn_hoist<BNL,RI,CI>(lane,gam,bet,sc,sh);
    if constexpr (CO==128){
        __shared__ ulonglong2 sW[CI*32];
        for(unsigned chunk=blockIdx.x; chunk<totc; chunk+=gridDim.x){
            if(threadIdx.x==0){
                int ko=0;
                while(chunk>=d_chunkpfx[ko+1]) ko++;
                s_ko=ko;
                int base=(int)(chunk-d_chunkpfx[ko])*PPB;
                s_base=base;
                s_cnt=min(PPB,(int)d_paircnt[ko]-base);
            }
            __syncthreads();
            int ko=s_ko;
            for(int i=threadIdx.x;i<CI*32;i+=blockDim.x){
                int ci=i>>5, ln=i&31;
                float4 w=*(const float4*)&W[(size_t)ko*CI*CO+(size_t)ci*CO+ln*4];
                sW[i]=make_ulonglong2(pk2(w.x,w.y),pk2(w.z,w.w));
            }
            __syncthreads();
            int cnt=s_cnt, base=s_base;
            for(int p2=warp*8;p2<cnt;p2+=nwarps*8){
                int dst[8];
                float r[8][RI];
                #pragma unroll
                for(int v=0;v<8;v++){
                    int idx=min(p2+v,cnt-1);
                    unsigned long long pr=d_pairs[(size_t)ko*TOT+base+idx];
                    dst[v]=(int)(pr>>32);
                    int src=(int)(pr&0xFFFFFFFFu);
                    #pragma unroll
                    for(int j=0;j<RI;j++)
                        r[v][j]=bn_apply<BNL>(in[(size_t)src*CI+lane+32*j],sc[j],sh[j]);
                }
                unsigned long long a0[8]={0,0,0,0,0,0,0,0},a1[8]={0,0,0,0,0,0,0,0};
                #pragma unroll
                for(int ci=0;ci<CI;ci++){
                    ulonglong2 w=sW[ci*32+lane];
                    #pragma unroll
                    for(int v=0;v<8;v++){
                        unsigned long long ff=dup2(__shfl_sync(0xffffffffu,r[v][ci>>5],ci&31));
                        a0[v]=ffma2(ff,w.x,a0[v]);
                        a1[v]=ffma2(ff,w.y,a1[v]);
                    }
                }
                #pragma unroll
                for(int v=0;v<8;v++) if(p2+v<cnt){
                    float o0,o1,o2,o3;
                    upk2(a0[v],o0,o1); upk2(a1[v],o2,o3);
                    red4(&out[(size_t)dst[v]*CO+lane*4],o0,o1,o2,o3);
                }
            }
            __syncthreads();
        }
    } else if constexpr (CO==64){
        __shared__ unsigned long long sW[CI*32];
        for(unsigned chunk=blockIdx.x; chunk<totc; chunk+=gridDim.x){
            if(threadIdx.x==0){
                int ko=0;
                while(chunk>=d_chunkpfx[ko+1]) ko++;
                s_ko=ko;
                int base=(int)(chunk-d_chunkpfx[ko])*PPB;
                s_base=base;
                s_cnt=min(PPB,(int)d_paircnt[ko]-base);
            }
            __syncthreads();
            int ko=s_ko;
            for(int i=threadIdx.x;i<CI*32;i+=blockDim.x){
                int ci=i>>5, ln=i&31;
                float2 w=*(const float2*)&W[(size_t)ko*CI*CO+(size_t)ci*CO+ln*2];
                sW[i]=pk2(w.x,w.y);
            }
            __syncthreads();
            int cnt=s_cnt, base=s_base;
            for(int p2=warp*8;p2<cnt;p2+=nwarps*8){
                int dst[8];
                float r[8];
                #pragma unroll
                for(int v=0;v<8;v++){
                    int idx=min(p2+v,cnt-1);
                    unsigned long long pr=d_pairs[(size_t)ko*TOT+base+idx];
                    dst[v]=(int)(pr>>32);
                    int src=(int)(pr&0xFFFFFFFFu);
                    r[v]=bn_apply<BNL>(in[(size_t)src*CI+lane],sc[0],sh[0]);
                }
                unsigned long long a0[8]={0,0,0,0,0,0,0,0};
                #pragma unroll
                for(int ci=0;ci<CI;ci++){
                    unsigned long long w=sW[ci*32+lane];
                    #pragma unroll
                    for(int v=0;v<8;v++)
                        a0[v]=ffma2(dup2(__shfl_sync(0xffffffffu,r[v],ci)),w,a0[v]);
                }
                #pragma unroll
                for(int v=0;v<8;v++) if(p2+v<cnt){
                    float o0,o1; upk2(a0[v],o0,o1);
                    red2(&out[(size_t)dst[v]*CO+lane*2],o0,o1);
                }
            }
            __syncthreads();
        }
    } else {
        __shared__ float Ws[CI*CO];
        for(unsigned chunk=blockIdx.x; chunk<totc; chunk+=gridDim.x){
            if(threadIdx.x==0){
                int ko=0;
                while(chunk>=d_chunkpfx[ko+1]) ko++;
                s_ko=ko;
                int base=(int)(chunk-d_chunkpfx[ko])*PPB;
                s_base=base;
                s_cnt=min(PPB,(int)d_paircnt[ko]-base);
            }
            __syncthreads();
            int ko=s_ko;
            for(int i=threadIdx.x;i<CI*CO;i+=blockDim.x) Ws[i]=W[(size_t)ko*CI*CO+i];
            __syncthreads();
            int cnt=s_cnt, base=s_base;
            for(int p2=warp*4;p2<cnt;p2+=nwarps*4){
                int dst[4];
                float r[4];
                #pragma unroll
                for(int v=0;v<4;v++){
                    int idx=min(p2+v,cnt-1);
                    unsigned long long pr=d_pairs[(size_t)ko*TOT+base+idx];
                    dst[v]=(int)(pr>>32);
                    int src=(int)(pr&0xFFFFFFFFu);
                    r[v]=(lane<CI)?bn_apply<BNL>(in[(size_t)src*CI+lane],sc[0],sh[0]):0.f;
                }
                float acc[4]={0,0,0,0};
                #pragma unroll
                for(int ci=0;ci<CI;ci++){
                    float w=Ws[ci*CO+lane];
                    #pragma unroll
                    for(int v=0;v<4;v++)
                        acc[v]+=__shfl_sync(0xffffffffu,r[v],ci)*w;
                }
                #pragma unroll
                for(int v=0;v<4;v++) if(p2+v<cnt)
                    atomicAdd(&out[(size_t)dst[v]*CO+lane],acc[v]);
            }
            __syncthreads();
        }
    }
}

// ---------- BN stats: contiguous-validity (pure streaming over valid prefix) ----------
template<int CO>
__global__ void k_stats(const float* __restrict__ h, int L){
    constexpr int TPS=CO/4;
    constexpr int SUBS=128/TPS;
    __shared__ int sCnt[BATCH];
    int tid=threadIdx.x;
    if(tid<BATCH) sCnt[tid]=d_batchcnt[tid];
    __syncthreads();
    int q=tid%TPS;
    int sub=tid/TPS;
    float s0=0,s1=0,s2=0,s3=0,t0=0,t1=0,t2=0,t3=0;
    for(int slot=blockIdx.x*SUBS+sub; slot<TOT; slot+=gridDim.x*SUBS){
        if((slot&0xFFFF)<sCnt[slot>>16]){
            float4 v=*(const float4*)&h[(size_t)slot*CO+q*4];
            s0+=v.x; s1+=v.y; s2+=v.z; s3+=v.w;
            t0+=v.x*v.x; t1+=v.y*v.y; t2+=v.z*v.z; t3+=v.w*v.w;
        }
    }
    __shared__ float ss[128][8];
    ss[tid][0]=s0; ss[tid][1]=s1; ss[tid][2]=s2; ss[tid][3]=s3;
    ss[tid][4]=t0; ss[tid][5]=t1; ss[tid][6]=t2; ss[tid][7]=t3;
    __syncthreads();
    if(sub==0){
        #pragma unroll 4
        for(int k=1;k<SUBS;k++){
            s0+=ss[k*TPS+q][0]; s1+=ss[k*TPS+q][1]; s2+=ss[k*TPS+q][2]; s3+=ss[k*TPS+q][3];
            t0+=ss[k*TPS+q][4]; t1+=ss[k*TPS+q][5]; t2+=ss[k*TPS+q][6]; t3+=ss[k*TPS+q][7];
        }
        int c=q*4;
        atomicAdd(&d_sumv[L][c+0],(double)s0);
        atomicAdd(&d_sumv[L][c+1],(double)s1);
        atomicAdd(&d_sumv[L][c+2],(double)s2);
        atomicAdd(&d_sumv[L][c+3],(double)s3);
        atomicAdd(&d_sumsq[L][c+0],(double)t0);
        atomicAdd(&d_sumsq[L][c+1],(double)t1);
        atomicAdd(&d_sumsq[L][c+2],(double)t2);
        atomicAdd(&d_sumsq[L][c+3],(double)t3);
    }
}

__global__ void k_bnfinal(int L,int CO){
    int c=threadIdx.x;
    if(c<CO){
        double n=(double)max(d_validcount,1);
        double m=d_sumv[L][c]/n;
        double var=d_sumsq[L][c]/n-m*m;
        if(var<0.0) var=0.0;
        d_bnmean[L][c]=(float)m;
        d_bnrstd[L][c]=rsqrtf((float)var+1e-5f);
    }
}

__global__ void k_out(const float* __restrict__ mask, float* __restrict__ out,
                      const float* __restrict__ gam, const float* __restrict__ bet){
    int stride=gridDim.x*blockDim.x;
    int q0=blockIdx.x*blockDim.x+threadIdx.x;
    int c4=(q0&31)*4;
    float a0=d_bnrstd[2][c4+0]*gam[c4+0], b0=bet[c4+0]-d_bnmean[2][c4+0]*a0;
    float a1=d_bnrstd[2][c4+1]*gam[c4+1], b1=bet[c4+1]-d_bnmean[2][c4+1]*a1;
    float a2=d_bnrstd[2][c4+2]*gam[c4+2], b2=bet[c4+2]-d_bnmean[2][c4+2]*a2;
    float a3=d_bnrstd[2][c4+3]*gam[c4+3], b3=bet[c4+3]-d_bnmean[2][c4+3]*a3;
    for(int q=q0; q<TOT*32; q+=stride){
        int g=q>>5;
        int slot=((g>>16)<<16)+d_invmap[g];
        float4 v=*(const float4*)&d_h3[(size_t)slot*128+c4];
        float m=mask[g];
        float4 o;
        o.x=fmaxf(fmaf(v.x,a0,b0),0.f)*m;
        o.y=fmaxf(fmaf(v.y,a1,b1),0.f)*m;
        o.z=fmaxf(fmaf(v.z,a2,b2),0.f)*m;
        o.w=fmaxf(fmaf(v.w,a3,b3),0.f)*m;
        *(float4*)&out[(size_t)q*4]=o;
    }
}

extern "C" void kernel_launch(void* const* d_in, const int* in_sizes, int n_in,
                              void* d_out, int out_size) {
    const float* xyz =(const float*)d_in[0];
    const float* feat=(const float*)d_in[1];
    const float* mask=(const float*)d_in[2];
    const float* W1=(const float*)d_in[3];
    const float* b1=(const float*)d_in[4];
    const float* g1=(const float*)d_in[5];
    const float* be1=(const float*)d_in[6];
    const float* W2=(const float*)d_in[7];
    const float* b2=(const float*)d_in[8];
    const float* g2=(const float*)d_in[9];
    const float* be2=(const float*)d_in[10];
    const float* W3=(const float*)d_in[11];
    const float* b3=(const float*)d_in[12];
    const float* g3=(const float*)d_in[13];
    const float* be3=(const float*)d_in[14];
    float* out=(float*)d_out;

    void *p_ki,*p_ko,*p_vi,*p_vo,*p_tmp;
    cudaGetSymbolAddress(&p_ki,d_keys_in);
    cudaGetSymbolAddress(&p_ko,d_keys_out);
    cudaGetSymbolAddress(&p_vi,d_vals_in);
    cudaGetSymbolAddress(&p_vo,d_vals_out);
    cudaGetSymbolAddress(&p_tmp,d_cub_temp);
    void *p_h1,*p_h2,*p_h3,*p_vf;
    cudaGetSymbolAddress(&p_h1,d_h1);
    cudaGetSymbolAddress(&p_h2,d_h2);
    cudaGetSymbolAddress(&p_h3,d_h3);
    cudaGetSymbolAddress(&p_vf,d_vfeat);
    float* h1=(float*)p_h1; float* h2=(float*)p_h2; float* h3=(float*)p_h3;
    float* vf=(float*)p_vf;

    k_init<<<1,384>>>();
    k_min<<<256,256>>>(xyz);
    k_keys<<<1024,256>>>(xyz);
    size_t tmp_bytes=32u<<20;
    // 25-bit keys: 22-bit compact code + 3-bit batch
    cub::DeviceRadixSort::SortPairs(p_tmp,tmp_bytes,
        (const unsigned*)p_ki,(unsigned*)p_ko,
        (const unsigned*)p_vi,(unsigned*)p_vo,
        TOT,0,25,(cudaStream_t)0);
    k_scan1<<<1024,512>>>();
    k_scan2<<<1,1024>>>();
    k_build<<<2048,256>>>(feat,mask);
    k_pairs<<<2048,256>>>();
    k_sched<<<1,1>>>();

    // Layer 1: 16 -> 32
    k_center<CIN,32,-1><<<2048,256>>>(vf,h1,W1,b1,nullptr,nullptr);
    k_scatter<CIN,32,-1><<<2048,256>>>(vf,h1,W1,nullptr,nullptr);
    k_stats<32><<<2048,128>>>(h1,0);
    k_bnfinal<<<1,128>>>(0,32);
    // Layer 2: 32 -> 64 (fuses BN0+relu on input)
    k_center<32,64,0><<<2048,256>>>(h1,h2,W2,b2,g1,be1);
    k_scatter<32,64,0><<<2048,256>>>(h1,h2,W2,g1,be1);
    k_stats<64><<<2048,128>>>(h2,1);
    k_bnfinal<<<1,128>>>(1,64);
    // Layer 3: 64 -> 128 (fuses BN1+relu on input)
    k_center<64,128,1><<<2048,256>>>(h2,h3,W3,b3,g2,be2);
    k_scatter<64,128,1><<<2048,256>>>(h2,h3,W3,g2,be2);
    k_stats<128><<<2048,128>>>(h3,2);
    k_bnfinal<<<1,128>>>(2,128);
    // Final: BN2+relu + gather by inv + mask
    k_out<<<8192,256>>>(mask,out,g3,be3);
    // Restore LUT to zeros for next replay
    k_unclear<<<1024,256>>>();
}